// round 8
// baseline (speedup 1.0000x reference)
#include <cuda_runtime.h>
#include <cuda_bf16.h>
#include <cstdint>
#include <cstddef>

#define NROWS 8192          // BATCH*NODE
#define DIM   128
#define FEAT  256           // 2*DIM
#define KDIM  8192
#define EPSC  1e-5f

// ---------------- scratch (__device__ globals: no allocations allowed) ----------------
__device__ float          g_X  [NROWS * DIM];          // elu output, row-major (8192x128)
__device__ __nv_bfloat16  g_Xhi[DIM * NROWS];          // transposed [feature][row]
__device__ __nv_bfloat16  g_Xlo[DIM * NROWS];
__device__ float          g_Lp0[NROWS * DIM];          // split-K partial 0
__device__ float          g_Lp1[NROWS * DIM];          // split-K partial 1
__device__ float          g_Lx [NROWS * DIM];          // L @ X (summed)
__device__ float          g_Y  [NROWS * DIM];          // block0 output
__device__ float          g_stats[2 * FEAT];           // colsum, colsumsq

__device__ __forceinline__ void split_bf16(float v, __nv_bfloat16& h, __nv_bfloat16& l) {
    h = __float2bfloat16(v);
    l = __float2bfloat16(v - __bfloat162float(h));
}
__device__ __forceinline__ uint32_t packbf(float e0, float e1) {
    // result: low 16 = bf16(e0), high 16 = bf16(e1)
    uint32_t r;
    asm("cvt.rn.bf16x2.f32 %0, %1, %2;" : "=r"(r) : "f"(e1), "f"(e0));
    return r;
}
__device__ __forceinline__ uint32_t s2u(const void* p) {
    uint32_t a;
    asm("{ .reg .u64 t; cvta.to.shared.u64 t, %1; cvt.u32.u64 %0, t; }" : "=r"(a) : "l"(p));
    return a;
}
__device__ __forceinline__ void cp16(uint32_t dst, const void* src) {
    asm volatile("cp.async.cg.shared.global [%0], [%1], 16;" :: "r"(dst), "l"(src) : "memory");
}
__device__ __forceinline__ void cp_commit() {
    asm volatile("cp.async.commit_group;" ::: "memory");
}
__device__ __forceinline__ void cp_wait_all() {
    asm volatile("cp.async.wait_group 0;" ::: "memory");
}
__device__ __forceinline__ void ldsm4(uint32_t* r, uint32_t addr) {
    asm volatile("ldmatrix.sync.aligned.m8n8.x4.shared.b16 {%0,%1,%2,%3}, [%4];"
                 : "=r"(r[0]), "=r"(r[1]), "=r"(r[2]), "=r"(r[3]) : "r"(addr));
}
__device__ __forceinline__ void mma16816(float* acc, const uint32_t* a, uint32_t b0, uint32_t b1) {
    asm volatile(
        "mma.sync.aligned.m16n8k16.row.col.f32.bf16.bf16.f32 "
        "{%0,%1,%2,%3}, {%4,%5,%6,%7}, {%8,%9}, {%0,%1,%2,%3};\n"
        : "+f"(acc[0]), "+f"(acc[1]), "+f"(acc[2]), "+f"(acc[3])
        : "r"(a[0]), "r"(a[1]), "r"(a[2]), "r"(a[3]), "r"(b0), "r"(b1));
}

// ---------------- kernel 1: ELU + bf16 hi/lo split + transpose ----------------
__global__ void elu_split_kernel(const float* __restrict__ src) {
    const float* __restrict__ s = src ? src : g_Y;
    __shared__ float tile[32][33];
    int r0 = blockIdx.x * 32, c0 = blockIdx.y * 32;
    int tx = threadIdx.x, ty = threadIdx.y;
#pragma unroll
    for (int i = 0; i < 4; i++) {
        int r = r0 + ty + i * 8, c = c0 + tx;
        float v = s[(size_t)r * DIM + c];
        v = v > 0.f ? v : expm1f(v);
        g_X[(size_t)r * DIM + c] = v;
        tile[ty + i * 8][tx] = v;
    }
    __syncthreads();
#pragma unroll
    for (int i = 0; i < 4; i++) {
        int c = c0 + ty + i * 8;   // feature
        int r = r0 + tx;           // row
        float v = tile[tx][ty + i * 8];
        __nv_bfloat16 h, l; split_bf16(v, h, l);
        g_Xhi[(size_t)c * NROWS + r] = h;
        g_Xlo[(size_t)c * NROWS + r] = l;
    }
    if (blockIdx.x == 0 && blockIdx.y == 0) {
        int tid = ty * 32 + tx;
        g_stats[tid] = 0.f;
        g_stats[tid + FEAT] = 0.f;
    }
}

// ---------------- kernel 2: big GEMM  Lx = L @ X  (mma.sync bf16 3-pass) ----------------
// Grid (64, 2): blockIdx.x = M tile (128 rows), blockIdx.y = K split (4096 each).
// 256 threads = 8 warps (4 over M x 2 over N), warp tile 32M x 64N.
// Double-buffered smem stages; A converted fp32->bf16 hi/lo in regs; B via cp.async.
#define TBM   128
#define TBK   32
#define TNIT  128             // 4096 / 32
#define ASTR  80              // bytes per 32-bf16 row (skew padding, conflict-free)
#define OFF_AHI 0
#define OFF_ALO 10240
#define OFF_BHI 20480
#define OFF_BLO 30720
#define STG_BYTES 40960
#define SMEM_BIG  (2 * STG_BYTES)

__global__ __launch_bounds__(256, 1) void big_gemm_mma(const float* __restrict__ L) {
    extern __shared__ char smem[];
    const uint32_t sb = s2u(smem);
    const int tid = threadIdx.x, lane = tid & 31, wid = tid >> 5;
    const int wm = (wid & 3) * 32;      // warp M offset
    const int wn = (wid >> 2) * 64;     // warp N offset
    const int mBase = blockIdx.x * TBM;
    const int kBase = blockIdx.y * 4096;
    float* __restrict__ outP = blockIdx.y ? g_Lp1 : g_Lp0;

    // producer coordinates (4 chunks each for A and B)
    int arow[4], ac4[4], bmat[4], bf_[4], bseg[4];
#pragma unroll
    for (int i = 0; i < 4; i++) {
        int idx = tid + i * 256;        // 0..1023
        arow[i] = idx >> 3; ac4[i] = idx & 7;          // A: 128 rows x 8 float4
        bmat[i] = idx >> 9;                             // 0 = hi, 1 = lo
        int rem = idx & 511;
        bf_[i] = rem >> 2; bseg[i] = rem & 3;           // B: 128 feats x 4 x 16B
    }

    float4 aReg[4];
    auto ldgA = [&](int kg) {
#pragma unroll
        for (int i = 0; i < 4; i++)
            aReg[i] = *(const float4*)(L + (size_t)(mBase + arow[i]) * KDIM + kg + ac4[i] * 4);
    };
    auto cpB = [&](uint32_t stg, int kg) {
#pragma unroll
        for (int i = 0; i < 4; i++) {
            const __nv_bfloat16* src = (bmat[i] ? g_Xlo : g_Xhi)
                                       + (size_t)bf_[i] * NROWS + kg + bseg[i] * 8;
            uint32_t dst = stg + (bmat[i] ? OFF_BLO : OFF_BHI) + bf_[i] * ASTR + bseg[i] * 16;
            cp16(dst, src);
        }
        cp_commit();
    };
    auto stsA = [&](char* stg) {
#pragma unroll
        for (int i = 0; i < 4; i++) {
            float4 v = aReg[i];
            uint32_t h0 = packbf(v.x, v.y), h1 = packbf(v.z, v.w);
            float l0a = v.x - __uint_as_float(h0 << 16);
            float l0b = v.y - __uint_as_float(h0 & 0xFFFF0000u);
            float l1a = v.z - __uint_as_float(h1 << 16);
            float l1b = v.w - __uint_as_float(h1 & 0xFFFF0000u);
            int off = arow[i] * ASTR + ac4[i] * 8;
            *(uint2*)(stg + OFF_AHI + off) = make_uint2(h0, h1);
            *(uint2*)(stg + OFF_ALO + off) = make_uint2(packbf(l0a, l0b), packbf(l1a, l1b));
        }
    };

    float acc[2][8][4];
#pragma unroll
    for (int mf = 0; mf < 2; mf++)
#pragma unroll
        for (int nf = 0; nf < 8; nf++)
#pragma unroll
            for (int j = 0; j < 4; j++) acc[mf][nf][j] = 0.f;

    // ldmatrix lane addressing: row = base + (lane&15), 16B-seg = lane>>4
    const int lrow = lane & 15, lseg = lane >> 4;

    // ---- prologue ----
    ldgA(kBase);
    cpB(sb, kBase);
    stsA(smem);
    cp_wait_all();
    __syncthreads();

    for (int it = 0; it < TNIT; it++) {
        const int cur = it & 1, nxt = cur ^ 1;
        const uint32_t sA = sb + cur * STG_BYTES;
        const bool more = (it + 1) < TNIT;
        if (more) {
            int kg = kBase + (it + 1) * TBK;
            ldgA(kg);
            cpB(sb + nxt * STG_BYTES, kg);
        }
        // ---- consume stage cur ----
#pragma unroll
        for (int kk = 0; kk < 2; kk++) {
            uint32_t ah[2][4], al[2][4], bh[4][4], bl[4][4];
#pragma unroll
            for (int mf = 0; mf < 2; mf++) {
                uint32_t addr = sA + OFF_AHI + (wm + mf * 16 + lrow) * ASTR + (kk * 2 + lseg) * 16;
                ldsm4(ah[mf], addr);
                ldsm4(al[mf], addr + (OFF_ALO - OFF_AHI));
            }
#pragma unroll
            for (int q = 0; q < 4; q++) {
                uint32_t addr = sA + OFF_BHI + (wn + q * 16 + lrow) * ASTR + (kk * 2 + lseg) * 16;
                ldsm4(bh[q], addr);
                ldsm4(bl[q], addr + (OFF_BLO - OFF_BHI));
            }
#pragma unroll
            for (int nf = 0; nf < 8; nf++) {
                const int q = nf >> 1, o = nf & 1;
                uint32_t b0h = bh[q][o], b1h = bh[q][o + 2];
                uint32_t b0l = bl[q][o], b1l = bl[q][o + 2];
#pragma unroll
                for (int mf = 0; mf < 2; mf++) {
                    mma16816(acc[mf][nf], ah[mf], b0h, b1h);   // hi*hi
                    mma16816(acc[mf][nf], ah[mf], b0l, b1l);   // hi*lo
                    mma16816(acc[mf][nf], al[mf], b0h, b1h);   // lo*hi
                }
            }
        }
        if (more) {
            stsA(smem + nxt * STG_BYTES);
            cp_wait_all();
        }
        __syncthreads();
    }

    // ---- epilogue ----
#pragma unroll
    for (int mf = 0; mf < 2; mf++) {
        const int r0 = mBase + wm + mf * 16 + (lane >> 2);
#pragma unroll
        for (int nf = 0; nf < 8; nf++) {
            const int col = wn + nf * 8 + (lane & 3) * 2;
            *(float2*)(outP + (size_t)r0 * DIM + col)       = make_float2(acc[mf][nf][0], acc[mf][nf][1]);
            *(float2*)(outP + (size_t)(r0 + 8) * DIM + col) = make_float2(acc[mf][nf][2], acc[mf][nf][3]);
        }
    }
}

// ---------------- kernel 3: split-K reduce + per-feature column stats ----------------
__global__ void stats_kernel() {
    int b = blockIdx.x;          // 32 blocks: 16 per matrix
    int mat = b >> 4;
    int rbase = (b & 15) * 512;
    int c = threadIdx.x;         // 128 threads = columns
    float s = 0.f, s2 = 0.f;
    if (mat == 0) {
#pragma unroll 4
        for (int r = 0; r < 512; r++) {
            float v = g_X[(size_t)(rbase + r) * DIM + c];
            s += v; s2 += v * v;
        }
    } else {
#pragma unroll 4
        for (int r = 0; r < 512; r++) {
            size_t i = (size_t)(rbase + r) * DIM + c;
            float v = g_Lp0[i] + g_Lp1[i];
            g_Lx[i] = v;
            s += v; s2 += v * v;
        }
    }
    atomicAdd(&g_stats[mat * DIM + c], s);
    atomicAdd(&g_stats[FEAT + mat * DIM + c], s2);
}

// ---------------- kernel 4: BN folded into Linear: out = h @ (W*s)^T + (b + W t) --------
__global__ __launch_bounds__(256) void small_gemm_kernel(
    const float* __restrict__ gamma, const float* __restrict__ beta,
    const float* __restrict__ W,     const float* __restrict__ bias,
    const float* __restrict__ residual, float* __restrict__ outp)
{
    float* __restrict__ out = outp ? outp : g_Y;
    __shared__ float sS[FEAT], sT[FEAT], sC[DIM];
    __shared__ float sH[64][33];
    __shared__ float sWt[32 * 132];    // transposed, padded: sWt[f*132 + d]

    const int tid = threadIdx.x;
    {
        int f = tid;  // exactly 256 threads
        float mu  = g_stats[f] * (1.f / NROWS);
        float var = g_stats[FEAT + f] * (1.f / NROWS) - mu * mu;
        float inv = rsqrtf(var + EPSC);
        float s = gamma[f] * inv;
        sS[f] = s;
        sT[f] = beta[f] - mu * s;
    }
    __syncthreads();
    if (tid < DIM) {
        float cb = bias[tid];
        for (int f = 0; f < FEAT; f++) cb += sT[f] * W[tid * FEAT + f];
        sC[tid] = cb;
    }
    __syncthreads();

    float acc[4][8];
#pragma unroll
    for (int r = 0; r < 4; r++)
#pragma unroll
        for (int c = 0; c < 8; c++) acc[r][c] = 0.f;

    const int rBase = blockIdx.x * 64;
    const int ti = tid >> 4, tj = tid & 15;

    for (int fc = 0; fc < FEAT; fc += 32) {
#pragma unroll
        for (int i = 0; i < 8; i++) {
            int idx = tid + i * 256;
            int row = idx >> 5, f = idx & 31;
            int gf = fc + f;
            float v = (gf < DIM) ? g_X [(size_t)(rBase + row) * DIM + gf]
                                 : g_Lx[(size_t)(rBase + row) * DIM + (gf - DIM)];
            sH[row][f] = v;
        }
#pragma unroll
        for (int i = 0; i < 16; i++) {
            int idx = tid + i * 256;          // 0..4095
            int f = idx & 31, d = idx >> 5;   // coalesced read along f
            int gf = fc + f;
            sWt[f * 132 + d] = W[d * FEAT + gf] * sS[gf];
        }
        __syncthreads();
#pragma unroll
        for (int f = 0; f < 32; f++) {
            float4 w0 = *(const float4*)&sWt[f * 132 + tj * 4];
            float4 w1 = *(const float4*)&sWt[f * 132 + 64 + tj * 4];
            float hv[4];
#pragma unroll
            for (int r = 0; r < 4; r++) hv[r] = sH[ti * 4 + r][f];
            float wv[8] = {w0.x, w0.y, w0.z, w0.w, w1.x, w1.y, w1.z, w1.w};
#pragma unroll
            for (int r = 0; r < 4; r++)
#pragma unroll
                for (int c = 0; c < 8; c++) acc[r][c] += hv[r] * wv[c];
        }
        __syncthreads();
    }

#pragma unroll
    for (int r = 0; r < 4; r++)
#pragma unroll
        for (int c = 0; c < 8; c++) {
            int row = rBase + ti * 4 + r;
            int col = (c < 4) ? (tj * 4 + c) : (64 + tj * 4 + (c - 4));
            float o = acc[r][c] + sC[col];
            if (residual) o += residual[(size_t)row * DIM + col];
            out[(size_t)row * DIM + col] = o;
        }
}

// ---------------- launch ----------------
extern "C" void kernel_launch(void* const* d_in, const int* in_sizes, int n_in,
                              void* d_out, int out_size)
{
    const float* L      = (const float*)d_in[0];
    // d_in[1] = mask (unused in forward)
    const float* inputs = (const float*)d_in[2];
    const float* bn0_g  = (const float*)d_in[3];
    const float* bn0_b  = (const float*)d_in[4];
    const float* fc0_w  = (const float*)d_in[5];
    const float* fc0_b  = (const float*)d_in[6];
    const float* bn1_g  = (const float*)d_in[7];
    const float* bn1_b  = (const float*)d_in[8];
    const float* fc1_w  = (const float*)d_in[9];
    const float* fc1_b  = (const float*)d_in[10];
    float* out = (float*)d_out;

    cudaFuncSetAttribute((const void*)big_gemm_mma,
                         cudaFuncAttributeMaxDynamicSharedMemorySize, SMEM_BIG);

    dim3 eg(NROWS / 32, DIM / 32), eb(32, 8);
    dim3 gg(NROWS / TBM, 2);

    // ---- block 0 ----
    elu_split_kernel<<<eg, eb>>>(inputs);                 // X = elu(inputs); zeroes stats
    big_gemm_mma<<<gg, 256, SMEM_BIG>>>(L);               // Lp0/Lp1 = split-K partials
    stats_kernel<<<32, 128>>>();                          // reduce partials + column stats
    small_gemm_kernel<<<NROWS / 64, 256>>>(bn0_g, bn0_b, fc0_w, fc0_b,
                                           nullptr, nullptr);   // -> g_Y

    // ---- block 1 ----
    elu_split_kernel<<<eg, eb>>>(nullptr);                // X = elu(g_Y); zeroes stats
    big_gemm_mma<<<gg, 256, SMEM_BIG>>>(L);
    stats_kernel<<<32, 128>>>();
    small_gemm_kernel<<<NROWS / 64, 256>>>(bn1_g, bn1_b, fc1_w, fc1_b,
                                           inputs, out);  // + residual -> d_out
}

// round 12
// speedup vs baseline: 1.4357x; 1.4357x over previous
#include <cuda_runtime.h>
#include <cuda_bf16.h>
#include <cstdint>
#include <cstddef>

#define NROWS 8192          // BATCH*NODE
#define DIM   128
#define FEAT  256           // 2*DIM
#define KDIM  8192
#define EPSC  1e-5f

// ---------------- scratch (__device__ globals: no allocations allowed) ----------------
__device__ float          g_X  [NROWS * DIM];          // elu output, row-major (8192x128)
__device__ __nv_bfloat16  g_Xhi[DIM * NROWS];          // transposed [feature][row]
__device__ __nv_bfloat16  g_Xlo[DIM * NROWS];
__device__ float          g_Lp0[NROWS * DIM];          // split-K partial 0
__device__ float          g_Lp1[NROWS * DIM];          // split-K partial 1
__device__ float          g_Lx [NROWS * DIM];          // L @ X (summed)
__device__ float          g_Y  [NROWS * DIM];          // block0 output
__device__ float          g_stats[2 * FEAT];           // colsum, colsumsq
__device__ float          g_fS[FEAT];                  // folded BN scale
__device__ float          g_fC[DIM];                   // folded bias

__device__ __forceinline__ void split_bf16(float v, __nv_bfloat16& h, __nv_bfloat16& l) {
    h = __float2bfloat16(v);
    l = __float2bfloat16(v - __bfloat162float(h));
}
__device__ __forceinline__ uint32_t packbf(float e0, float e1) {
    // result: low 16 = bf16(e0), high 16 = bf16(e1)
    uint32_t r;
    asm("cvt.rn.bf16x2.f32 %0, %1, %2;" : "=r"(r) : "f"(e1), "f"(e0));
    return r;
}
__device__ __forceinline__ uint32_t s2u(const void* p) {
    uint32_t a;
    asm("{ .reg .u64 t; cvta.to.shared.u64 t, %1; cvt.u32.u64 %0, t; }" : "=r"(a) : "l"(p));
    return a;
}
__device__ __forceinline__ void cp16(uint32_t dst, const void* src) {
    asm volatile("cp.async.cg.shared.global [%0], [%1], 16;" :: "r"(dst), "l"(src) : "memory");
}
__device__ __forceinline__ void cp_commit() {
    asm volatile("cp.async.commit_group;" ::: "memory");
}
__device__ __forceinline__ void cp_wait_all() {
    asm volatile("cp.async.wait_group 0;" ::: "memory");
}
__device__ __forceinline__ void ldsm4(uint32_t* r, uint32_t addr) {
    asm volatile("ldmatrix.sync.aligned.m8n8.x4.shared.b16 {%0,%1,%2,%3}, [%4];"
                 : "=r"(r[0]), "=r"(r[1]), "=r"(r[2]), "=r"(r[3]) : "r"(addr));
}
__device__ __forceinline__ void mma16816(float* acc, const uint32_t* a, uint32_t b0, uint32_t b1) {
    asm volatile(
        "mma.sync.aligned.m16n8k16.row.col.f32.bf16.bf16.f32 "
        "{%0,%1,%2,%3}, {%4,%5,%6,%7}, {%8,%9}, {%0,%1,%2,%3};\n"
        : "+f"(acc[0]), "+f"(acc[1]), "+f"(acc[2]), "+f"(acc[3])
        : "r"(a[0]), "r"(a[1]), "r"(a[2]), "r"(a[3]), "r"(b0), "r"(b1));
}

// ---------------- kernel 1: ELU + bf16 hi/lo split + transpose ----------------
__global__ void elu_split_kernel(const float* __restrict__ src) {
    const float* __restrict__ s = src ? src : g_Y;
    __shared__ float tile[32][33];
    int r0 = blockIdx.x * 32, c0 = blockIdx.y * 32;
    int tx = threadIdx.x, ty = threadIdx.y;
#pragma unroll
    for (int i = 0; i < 4; i++) {
        int r = r0 + ty + i * 8, c = c0 + tx;
        float v = s[(size_t)r * DIM + c];
        v = v > 0.f ? v : expm1f(v);
        g_X[(size_t)r * DIM + c] = v;
        tile[ty + i * 8][tx] = v;
    }
    __syncthreads();
#pragma unroll
    for (int i = 0; i < 4; i++) {
        int c = c0 + ty + i * 8;   // feature
        int r = r0 + tx;           // row
        float v = tile[tx][ty + i * 8];
        __nv_bfloat16 h, l; split_bf16(v, h, l);
        g_Xhi[(size_t)c * NROWS + r] = h;
        g_Xlo[(size_t)c * NROWS + r] = l;
    }
    if (blockIdx.x == 0 && blockIdx.y == 0) {
        int tid = ty * 32 + tx;
        g_stats[tid] = 0.f;
        g_stats[tid + FEAT] = 0.f;
    }
}

// ---------------- kernel 2: big GEMM  Lx = L @ X  (mma.sync bf16 3-pass) ----------------
// Grid (64, 2): blockIdx.x = M tile (128 rows), blockIdx.y = K split (4096 each).
// 256 threads = 8 warps (4 over M x 2 over N), warp tile 32M x 64N.
#define TBM   128
#define TBK   32
#define TNIT  128             // 4096 / 32
#define ASTR  80              // bytes per 32-bf16 row (skew padding, conflict-free)
#define OFF_AHI 0
#define OFF_ALO 10240
#define OFF_BHI 20480
#define OFF_BLO 30720
#define STG_BYTES 40960
#define SMEM_BIG  (2 * STG_BYTES)

__global__ __launch_bounds__(256, 1) void big_gemm_mma(const float* __restrict__ L) {
    extern __shared__ char smem[];
    const uint32_t sb = s2u(smem);
    const int tid = threadIdx.x, lane = tid & 31, wid = tid >> 5;
    const int wm = (wid & 3) * 32;      // warp M offset
    const int wn = (wid >> 2) * 64;     // warp N offset
    const int mBase = blockIdx.x * TBM;
    const int kBase = blockIdx.y * 4096;
    float* __restrict__ outP = blockIdx.y ? g_Lp1 : g_Lp0;

    // producer coordinates (4 chunks each for A and B)
    int arow[4], ac4[4], bmat[4], bf_[4], bseg[4];
#pragma unroll
    for (int i = 0; i < 4; i++) {
        int idx = tid + i * 256;        // 0..1023
        arow[i] = idx >> 3; ac4[i] = idx & 7;          // A: 128 rows x 8 float4
        bmat[i] = idx >> 9;                             // 0 = hi, 1 = lo
        int rem = idx & 511;
        bf_[i] = rem >> 2; bseg[i] = rem & 3;           // B: 128 feats x 4 x 16B
    }

    float4 aReg[4];
    auto ldgA = [&](int kg) {
#pragma unroll
        for (int i = 0; i < 4; i++)
            aReg[i] = *(const float4*)(L + (size_t)(mBase + arow[i]) * KDIM + kg + ac4[i] * 4);
    };
    auto cpB = [&](uint32_t stg, int kg) {
#pragma unroll
        for (int i = 0; i < 4; i++) {
            const __nv_bfloat16* src = (bmat[i] ? g_Xlo : g_Xhi)
                                       + (size_t)bf_[i] * NROWS + kg + bseg[i] * 8;
            uint32_t dst = stg + (bmat[i] ? OFF_BLO : OFF_BHI) + bf_[i] * ASTR + bseg[i] * 16;
            cp16(dst, src);
        }
        cp_commit();
    };
    auto stsA = [&](char* stg) {
#pragma unroll
        for (int i = 0; i < 4; i++) {
            float4 v = aReg[i];
            uint32_t h0 = packbf(v.x, v.y), h1 = packbf(v.z, v.w);
            float l0a = v.x - __uint_as_float(h0 << 16);
            float l0b = v.y - __uint_as_float(h0 & 0xFFFF0000u);
            float l1a = v.z - __uint_as_float(h1 << 16);
            float l1b = v.w - __uint_as_float(h1 & 0xFFFF0000u);
            int off = arow[i] * ASTR + ac4[i] * 8;
            *(uint2*)(stg + OFF_AHI + off) = make_uint2(h0, h1);
            *(uint2*)(stg + OFF_ALO + off) = make_uint2(packbf(l0a, l0b), packbf(l1a, l1b));
        }
    };

    float acc[2][8][4];
#pragma unroll
    for (int mf = 0; mf < 2; mf++)
#pragma unroll
        for (int nf = 0; nf < 8; nf++)
#pragma unroll
            for (int j = 0; j < 4; j++) acc[mf][nf][j] = 0.f;

    const int lrow = lane & 15, lseg = lane >> 4;

    // ---- prologue ----
    ldgA(kBase);
    cpB(sb, kBase);
    stsA(smem);
    cp_wait_all();
    __syncthreads();

    for (int it = 0; it < TNIT; it++) {
        const int cur = it & 1, nxt = cur ^ 1;
        const uint32_t sA = sb + cur * STG_BYTES;
        const bool more = (it + 1) < TNIT;
        if (more) {
            int kg = kBase + (it + 1) * TBK;
            ldgA(kg);
            cpB(sb + nxt * STG_BYTES, kg);
        }
        // ---- consume stage cur ----
#pragma unroll
        for (int kk = 0; kk < 2; kk++) {
            uint32_t ah[2][4], al[2][4], bh[4][4], bl[4][4];
#pragma unroll
            for (int mf = 0; mf < 2; mf++) {
                uint32_t addr = sA + OFF_AHI + (wm + mf * 16 + lrow) * ASTR + (kk * 2 + lseg) * 16;
                ldsm4(ah[mf], addr);
                ldsm4(al[mf], addr + (OFF_ALO - OFF_AHI));
            }
#pragma unroll
            for (int q = 0; q < 4; q++) {
                uint32_t addr = sA + OFF_BHI + (wn + q * 16 + lrow) * ASTR + (kk * 2 + lseg) * 16;
                ldsm4(bh[q], addr);
                ldsm4(bl[q], addr + (OFF_BLO - OFF_BHI));
            }
#pragma unroll
            for (int nf = 0; nf < 8; nf++) {
                const int q = nf >> 1, o = nf & 1;
                uint32_t b0h = bh[q][o], b1h = bh[q][o + 2];
                uint32_t b0l = bl[q][o], b1l = bl[q][o + 2];
#pragma unroll
                for (int mf = 0; mf < 2; mf++) {
                    mma16816(acc[mf][nf], ah[mf], b0h, b1h);   // hi*hi
                    mma16816(acc[mf][nf], ah[mf], b0l, b1l);   // hi*lo
                    mma16816(acc[mf][nf], al[mf], b0h, b1h);   // lo*hi
                }
            }
        }
        if (more) {
            stsA(smem + nxt * STG_BYTES);
            cp_wait_all();
        }
        __syncthreads();
    }

    // ---- epilogue ----
#pragma unroll
    for (int mf = 0; mf < 2; mf++) {
        const int r0 = mBase + wm + mf * 16 + (lane >> 2);
#pragma unroll
        for (int nf = 0; nf < 8; nf++) {
            const int col = wn + nf * 8 + (lane & 3) * 2;
            *(float2*)(outP + (size_t)r0 * DIM + col)       = make_float2(acc[mf][nf][0], acc[mf][nf][1]);
            *(float2*)(outP + (size_t)(r0 + 8) * DIM + col) = make_float2(acc[mf][nf][2], acc[mf][nf][3]);
        }
    }
}

// ---------------- kernel 3: split-K reduce + per-feature column stats ----------------
// 256 blocks (128 per matrix), 64 rows each: ~2 MB in flight -> DRAM-BW bound.
__global__ void stats_kernel() {
    int b = blockIdx.x;
    int mat = b >> 7;
    int rbase = (b & 127) * 64;
    int c = threadIdx.x;         // 128 threads = columns
    float s = 0.f, s2 = 0.f;
    if (mat == 0) {
#pragma unroll 8
        for (int r = 0; r < 64; r++) {
            float v = g_X[(size_t)(rbase + r) * DIM + c];
            s += v; s2 += v * v;
        }
    } else {
#pragma unroll 8
        for (int r = 0; r < 64; r++) {
            size_t i = (size_t)(rbase + r) * DIM + c;
            float v = g_Lp0[i] + g_Lp1[i];
            g_Lx[i] = v;
            s += v; s2 += v * v;
        }
    }
    atomicAdd(&g_stats[mat * DIM + c], s);
    atomicAdd(&g_stats[FEAT + mat * DIM + c], s2);
}

// ---------------- kernel 3b: fold BN constants once: g_fS[f], g_fC[d] ----------------
__global__ void fold_kernel(const float* __restrict__ gamma, const float* __restrict__ beta,
                            const float* __restrict__ W,     const float* __restrict__ bias)
{
    __shared__ float sT[FEAT];
    __shared__ float part[256];
    int tid = threadIdx.x;       // 256 threads
    {
        float mu  = g_stats[tid] * (1.f / NROWS);
        float var = g_stats[FEAT + tid] * (1.f / NROWS) - mu * mu;
        float inv = rsqrtf(var + EPSC);
        float s = gamma[tid] * inv;
        g_fS[tid] = s;
        sT[tid] = beta[tid] - mu * s;
    }
    __syncthreads();
    int d = tid & 127, h = tid >> 7;
    const float* w = W + (size_t)d * FEAT + h * 128;
    float acc0 = 0.f, acc1 = 0.f;
#pragma unroll 8
    for (int f = 0; f < 128; f += 2) {
        acc0 += sT[h * 128 + f] * w[f];
        acc1 += sT[h * 128 + f + 1] * w[f + 1];
    }
    part[tid] = acc0 + acc1;
    __syncthreads();
    if (tid < DIM) g_fC[tid] = bias[tid] + part[tid] + part[tid + 128];
}

// ---------------- kernel 4: BN folded into Linear: out = h @ (W*s)^T + c ----------------
// 128 blocks x 512 threads, 64 rows/block, 2 rows x 8 cols per thread.
__global__ __launch_bounds__(512) void small_gemm_kernel(
    const float* __restrict__ W, const float* __restrict__ residual, float* __restrict__ outp)
{
    float* __restrict__ out = outp ? outp : g_Y;
    __shared__ float sS[FEAT], sC[DIM];
    __shared__ float sH[64][33];
    __shared__ float sWt[32 * 132];    // transposed, padded: sWt[f*132 + d]

    const int tid = threadIdx.x;
    if (tid < FEAT) sS[tid] = g_fS[tid];
    else if (tid < FEAT + DIM) sC[tid - FEAT] = g_fC[tid - FEAT];
    __syncthreads();

    float acc[2][8];
#pragma unroll
    for (int r = 0; r < 2; r++)
#pragma unroll
        for (int c = 0; c < 8; c++) acc[r][c] = 0.f;

    const int rBase = blockIdx.x * 64;
    const int ti = tid >> 4, tj = tid & 15;    // ti 0..31 (2 rows each), tj 0..15 (8 cols)

    for (int fc = 0; fc < FEAT; fc += 32) {
#pragma unroll
        for (int i = 0; i < 4; i++) {
            int idx = tid + i * 512;            // 0..2047
            int row = idx >> 5, f = idx & 31;
            int gf = fc + f;
            float v = (gf < DIM) ? g_X [(size_t)(rBase + row) * DIM + gf]
                                 : g_Lx[(size_t)(rBase + row) * DIM + (gf - DIM)];
            sH[row][f] = v;
        }
#pragma unroll
        for (int i = 0; i < 8; i++) {
            int idx = tid + i * 512;            // 0..4095
            int f = idx & 31, d = idx >> 5;     // coalesced read along f
            int gf = fc + f;
            sWt[f * 132 + d] = W[d * FEAT + gf] * sS[gf];
        }
        __syncthreads();
#pragma unroll
        for (int f = 0; f < 32; f++) {
            float4 w0 = *(const float4*)&sWt[f * 132 + tj * 4];
            float4 w1 = *(const float4*)&sWt[f * 132 + 64 + tj * 4];
            float hv0 = sH[ti * 2 + 0][f];
            float hv1 = sH[ti * 2 + 1][f];
            float wv[8] = {w0.x, w0.y, w0.z, w0.w, w1.x, w1.y, w1.z, w1.w};
#pragma unroll
            for (int c = 0; c < 8; c++) {
                acc[0][c] += hv0 * wv[c];
                acc[1][c] += hv1 * wv[c];
            }
        }
        __syncthreads();
    }

#pragma unroll
    for (int r = 0; r < 2; r++)
#pragma unroll
        for (int c = 0; c < 8; c++) {
            int row = rBase + ti * 2 + r;
            int col = (c < 4) ? (tj * 4 + c) : (64 + tj * 4 + (c - 4));
            float o = acc[r][c] + sC[col];
            if (residual) o += residual[(size_t)row * DIM + col];
            out[(size_t)row * DIM + col] = o;
        }
}

// ---------------- launch ----------------
extern "C" void kernel_launch(void* const* d_in, const int* in_sizes, int n_in,
                              void* d_out, int out_size)
{
    const float* L      = (const float*)d_in[0];
    // d_in[1] = mask (unused in forward)
    const float* inputs = (const float*)d_in[2];
    const float* bn0_g  = (const float*)d_in[3];
    const float* bn0_b  = (const float*)d_in[4];
    const float* fc0_w  = (const float*)d_in[5];
    const float* fc0_b  = (const float*)d_in[6];
    const float* bn1_g  = (const float*)d_in[7];
    const float* bn1_b  = (const float*)d_in[8];
    const float* fc1_w  = (const float*)d_in[9];
    const float* fc1_b  = (const float*)d_in[10];
    float* out = (float*)d_out;

    cudaFuncSetAttribute((const void*)big_gemm_mma,
                         cudaFuncAttributeMaxDynamicSharedMemorySize, SMEM_BIG);

    dim3 eg(NROWS / 32, DIM / 32), eb(32, 8);
    dim3 gg(NROWS / TBM, 2);

    // ---- block 0 ----
    elu_split_kernel<<<eg, eb>>>(inputs);                 // X = elu(inputs); zeroes stats
    big_gemm_mma<<<gg, 256, SMEM_BIG>>>(L);               // Lp0/Lp1 = split-K partials
    stats_kernel<<<256, 128>>>();                         // reduce partials + column stats
    fold_kernel<<<1, 256>>>(bn0_g, bn0_b, fc0_w, fc0_b);  // g_fS, g_fC
    small_gemm_kernel<<<NROWS / 64, 512>>>(fc0_w, nullptr, nullptr);   // -> g_Y

    // ---- block 1 ----
    elu_split_kernel<<<eg, eb>>>(nullptr);                // X = elu(g_Y); zeroes stats
    big_gemm_mma<<<gg, 256, SMEM_BIG>>>(L);
    stats_kernel<<<256, 128>>>();
    fold_kernel<<<1, 256>>>(bn1_g, bn1_b, fc1_w, fc1_b);
    small_gemm_kernel<<<NROWS / 64, 512>>>(fc1_w, inputs, out);  // + residual -> d_out
}

// round 16
// speedup vs baseline: 1.8675x; 1.3008x over previous
#include <cuda_runtime.h>
#include <cuda_bf16.h>
#include <cuda_fp16.h>
#include <cstdint>
#include <cstddef>

#define NROWS 8192          // BATCH*NODE
#define DIM   128
#define FEAT  256           // 2*DIM
#define KDIM  8192
#define EPSC  1e-5f

// ---------------- scratch (__device__ globals: no allocations allowed) ----------------
__device__ float   g_X  [NROWS * DIM];          // elu output, row-major (8192x128)
__device__ __half  g_Xhi[DIM * NROWS];          // transposed [feature][row], fp16 hi
__device__ __half  g_Xlo[DIM * NROWS];          // fp16 lo  (X - hi)
__device__ float   g_Lp0[NROWS * DIM];          // split-K partial 0
__device__ float   g_Lp1[NROWS * DIM];          // split-K partial 1
__device__ float   g_Lx [NROWS * DIM];          // L @ X (summed)
__device__ float   g_Y  [NROWS * DIM];          // block0 output
__device__ float   g_stats[2 * FEAT];           // colsum, colsumsq
__device__ float   g_fS[FEAT];                  // folded BN scale
__device__ float   g_fC[DIM];                   // folded bias

__device__ __forceinline__ uint32_t packh(float e0, float e1) {
    // result: low 16 = fp16(e0), high 16 = fp16(e1)
    uint32_t r;
    asm("cvt.rn.f16x2.f32 %0, %1, %2;" : "=r"(r) : "f"(e1), "f"(e0));
    return r;
}
__device__ __forceinline__ uint32_t s2u(const void* p) {
    uint32_t a;
    asm("{ .reg .u64 t; cvta.to.shared.u64 t, %1; cvt.u32.u64 %0, t; }" : "=r"(a) : "l"(p));
    return a;
}
__device__ __forceinline__ void cp16(uint32_t dst, const void* src) {
    asm volatile("cp.async.cg.shared.global [%0], [%1], 16;" :: "r"(dst), "l"(src) : "memory");
}
__device__ __forceinline__ void cp_commit() {
    asm volatile("cp.async.commit_group;" ::: "memory");
}
__device__ __forceinline__ void cp_wait_all() {
    asm volatile("cp.async.wait_group 0;" ::: "memory");
}
__device__ __forceinline__ void ldsm4(uint32_t* r, uint32_t addr) {
    asm volatile("ldmatrix.sync.aligned.m8n8.x4.shared.b16 {%0,%1,%2,%3}, [%4];"
                 : "=r"(r[0]), "=r"(r[1]), "=r"(r[2]), "=r"(r[3]) : "r"(addr));
}
__device__ __forceinline__ void mma16816h(float* acc, const uint32_t* a, uint32_t b0, uint32_t b1) {
    asm volatile(
        "mma.sync.aligned.m16n8k16.row.col.f32.f16.f16.f32 "
        "{%0,%1,%2,%3}, {%4,%5,%6,%7}, {%8,%9}, {%0,%1,%2,%3};\n"
        : "+f"(acc[0]), "+f"(acc[1]), "+f"(acc[2]), "+f"(acc[3])
        : "r"(a[0]), "r"(a[1]), "r"(a[2]), "r"(a[3]), "r"(b0), "r"(b1));
}

// ---------------- kernel 1: ELU + fp16 hi/lo split + transpose ----------------
__global__ void elu_split_kernel(const float* __restrict__ src) {
    const float* __restrict__ s = src ? src : g_Y;
    __shared__ float tile[32][33];
    int r0 = blockIdx.x * 32, c0 = blockIdx.y * 32;
    int tx = threadIdx.x, ty = threadIdx.y;
#pragma unroll
    for (int i = 0; i < 4; i++) {
        int r = r0 + ty + i * 8, c = c0 + tx;
        float v = s[(size_t)r * DIM + c];
        v = v > 0.f ? v : expm1f(v);
        g_X[(size_t)r * DIM + c] = v;
        tile[ty + i * 8][tx] = v;
    }
    __syncthreads();
#pragma unroll
    for (int i = 0; i < 4; i++) {
        int c = c0 + ty + i * 8;   // feature
        int r = r0 + tx;           // row
        float v = tile[tx][ty + i * 8];
        __half h = __float2half_rn(v);
        float l = v - __half2float(h);
        g_Xhi[(size_t)c * NROWS + r] = h;
        g_Xlo[(size_t)c * NROWS + r] = __float2half_rn(l);
    }
    if (blockIdx.x == 0 && blockIdx.y == 0) {
        int tid = ty * 32 + tx;
        g_stats[tid] = 0.f;
        g_stats[tid + FEAT] = 0.f;
    }
}

// ---------------- kernel 2: big GEMM  Lx = L @ X  (mma.sync fp16 2-pass) ----------------
// Grid (64, 2): blockIdx.x = M tile (128 rows), blockIdx.y = K split (4096 each).
// 256 threads = 8 warps (4 over M x 2 over N), warp tile 32M x 64N.
// A = fp16 single (error 2^-11, dropped), B = fp16 hi + lo (error 2^-22).
#define TBM   128
#define TBK   32
#define TNIT  128             // 4096 / 32
#define ASTR  80              // bytes per 32-fp16 row (skew padding, conflict-free)
#define OFF_AH  0
#define OFF_BHI 10240
#define OFF_BLO 20480
#define STG_BYTES 30720
#define SMEM_BIG  (2 * STG_BYTES)

__global__ __launch_bounds__(256, 1) void big_gemm_mma(const float* __restrict__ L) {
    extern __shared__ char smem[];
    const uint32_t sb = s2u(smem);
    const int tid = threadIdx.x, lane = tid & 31, wid = tid >> 5;
    const int wm = (wid & 3) * 32;      // warp M offset
    const int wn = (wid >> 2) * 64;     // warp N offset
    const int mBase = blockIdx.x * TBM;
    const int kBase = blockIdx.y * 4096;
    float* __restrict__ outP = blockIdx.y ? g_Lp1 : g_Lp0;

    // producer coordinates (4 chunks each for A and B)
    int arow[4], ac4[4], bmat[4], bf_[4], bseg[4];
#pragma unroll
    for (int i = 0; i < 4; i++) {
        int idx = tid + i * 256;        // 0..1023
        arow[i] = idx >> 3; ac4[i] = idx & 7;          // A: 128 rows x 8 float4
        bmat[i] = idx >> 9;                             // 0 = hi, 1 = lo
        int rem = idx & 511;
        bf_[i] = rem >> 2; bseg[i] = rem & 3;           // B: 128 feats x 4 x 16B
    }

    float4 aReg[4];
    auto ldgA = [&](int kg) {
#pragma unroll
        for (int i = 0; i < 4; i++)
            aReg[i] = *(const float4*)(L + (size_t)(mBase + arow[i]) * KDIM + kg + ac4[i] * 4);
    };
    auto cpB = [&](uint32_t stg, int kg) {
#pragma unroll
        for (int i = 0; i < 4; i++) {
            const __half* src = (bmat[i] ? g_Xlo : g_Xhi)
                                + (size_t)bf_[i] * NROWS + kg + bseg[i] * 8;
            uint32_t dst = stg + (bmat[i] ? OFF_BLO : OFF_BHI) + bf_[i] * ASTR + bseg[i] * 16;
            cp16(dst, src);
        }
        cp_commit();
    };
    auto stsA = [&](char* stg) {
#pragma unroll
        for (int i = 0; i < 4; i++) {
            float4 v = aReg[i];
            uint32_t h0 = packh(v.x, v.y), h1 = packh(v.z, v.w);
            int off = arow[i] * ASTR + ac4[i] * 8;
            *(uint2*)(stg + OFF_AH + off) = make_uint2(h0, h1);
        }
    };

    float acc[2][8][4];
#pragma unroll
    for (int mf = 0; mf < 2; mf++)
#pragma unroll
        for (int nf = 0; nf < 8; nf++)
#pragma unroll
            for (int j = 0; j < 4; j++) acc[mf][nf][j] = 0.f;

    const int lrow = lane & 15, lseg = lane >> 4;

    // ---- prologue ----
    ldgA(kBase);
    cpB(sb, kBase);
    stsA(smem);
    cp_wait_all();
    __syncthreads();

    for (int it = 0; it < TNIT; it++) {
        const int cur = it & 1, nxt = cur ^ 1;
        const uint32_t sA = sb + cur * STG_BYTES;
        const bool more = (it + 1) < TNIT;
        if (more) {
            int kg = kBase + (it + 1) * TBK;
            ldgA(kg);
            cpB(sb + nxt * STG_BYTES, kg);
        }
        // ---- consume stage cur ----
#pragma unroll
        for (int kk = 0; kk < 2; kk++) {
            uint32_t ah[2][4], bh[4][4], bl[4][4];
#pragma unroll
            for (int mf = 0; mf < 2; mf++) {
                uint32_t addr = sA + OFF_AH + (wm + mf * 16 + lrow) * ASTR + (kk * 2 + lseg) * 16;
                ldsm4(ah[mf], addr);
            }
#pragma unroll
            for (int q = 0; q < 4; q++) {
                uint32_t addr = sA + OFF_BHI + (wn + q * 16 + lrow) * ASTR + (kk * 2 + lseg) * 16;
                ldsm4(bh[q], addr);
                ldsm4(bl[q], addr + (OFF_BLO - OFF_BHI));
            }
#pragma unroll
            for (int nf = 0; nf < 8; nf++) {
                const int q = nf >> 1, o = nf & 1;
                uint32_t b0h = bh[q][o], b1h = bh[q][o + 2];
                uint32_t b0l = bl[q][o], b1l = bl[q][o + 2];
#pragma unroll
                for (int mf = 0; mf < 2; mf++) {
                    mma16816h(acc[mf][nf], ah[mf], b0h, b1h);   // A * B_hi
                    mma16816h(acc[mf][nf], ah[mf], b0l, b1l);   // A * B_lo
                }
            }
        }
        if (more) {
            stsA(smem + nxt * STG_BYTES);
            cp_wait_all();
        }
        __syncthreads();
    }

    // ---- epilogue ----
#pragma unroll
    for (int mf = 0; mf < 2; mf++) {
        const int r0 = mBase + wm + mf * 16 + (lane >> 2);
#pragma unroll
        for (int nf = 0; nf < 8; nf++) {
            const int col = wn + nf * 8 + (lane & 3) * 2;
            *(float2*)(outP + (size_t)r0 * DIM + col)       = make_float2(acc[mf][nf][0], acc[mf][nf][1]);
            *(float2*)(outP + (size_t)(r0 + 8) * DIM + col) = make_float2(acc[mf][nf][2], acc[mf][nf][3]);
        }
    }
}

// ---------------- kernel 3: split-K reduce + per-feature column stats ----------------
// 256 blocks (128 per matrix), 64 rows each: ~2 MB in flight -> DRAM-BW bound.
__global__ void stats_kernel() {
    int b = blockIdx.x;
    int mat = b >> 7;
    int rbase = (b & 127) * 64;
    int c = threadIdx.x;         // 128 threads = columns
    float s = 0.f, s2 = 0.f;
    if (mat == 0) {
#pragma unroll 8
        for (int r = 0; r < 64; r++) {
            float v = g_X[(size_t)(rbase + r) * DIM + c];
            s += v; s2 += v * v;
        }
    } else {
#pragma unroll 8
        for (int r = 0; r < 64; r++) {
            size_t i = (size_t)(rbase + r) * DIM + c;
            float v = g_Lp0[i] + g_Lp1[i];
            g_Lx[i] = v;
            s += v; s2 += v * v;
        }
    }
    atomicAdd(&g_stats[mat * DIM + c], s);
    atomicAdd(&g_stats[FEAT + mat * DIM + c], s2);
}

// ---------------- kernel 3b: fold BN constants: g_fS[f], g_fC[d] (128 blocks) ----------
__global__ void fold_kernel(const float* __restrict__ gamma, const float* __restrict__ beta,
                            const float* __restrict__ W,     const float* __restrict__ bias)
{
    __shared__ float sT[FEAT];
    __shared__ float red[8];
    const int tid = threadIdx.x;       // 256 threads
    const int d = blockIdx.x;          // 128 blocks, one output channel each
    {
        float mu  = g_stats[tid] * (1.f / NROWS);
        float var = g_stats[FEAT + tid] * (1.f / NROWS) - mu * mu;
        float inv = rsqrtf(var + EPSC);
        float s = gamma[tid] * inv;
        if (d == 0) g_fS[tid] = s;
        sT[tid] = beta[tid] - mu * s;
    }
    __syncthreads();
    float p = sT[tid] * W[(size_t)d * FEAT + tid];
#pragma unroll
    for (int o = 16; o > 0; o >>= 1) p += __shfl_xor_sync(0xFFFFFFFFu, p, o);
    if ((tid & 31) == 0) red[tid >> 5] = p;
    __syncthreads();
    if (tid == 0) {
        float t = 0.f;
#pragma unroll
        for (int w = 0; w < 8; w++) t += red[w];
        g_fC[d] = bias[d] + t;
    }
}

// ---------------- kernel 4: BN folded into Linear: out = h @ (W*s)^T + c ----------------
// 128 blocks x 512 threads, 64 rows/block, 2 rows x 8 cols per thread.
__global__ __launch_bounds__(512) void small_gemm_kernel(
    const float* __restrict__ W, const float* __restrict__ residual, float* __restrict__ outp)
{
    float* __restrict__ out = outp ? outp : g_Y;
    __shared__ float sS[FEAT], sC[DIM];
    __shared__ float sH[64][33];
    __shared__ float sWt[32 * 132];    // transposed, padded: sWt[f*132 + d]

    const int tid = threadIdx.x;
    if (tid < FEAT) sS[tid] = g_fS[tid];
    else if (tid < FEAT + DIM) sC[tid - FEAT] = g_fC[tid - FEAT];
    __syncthreads();

    float acc[2][8];
#pragma unroll
    for (int r = 0; r < 2; r++)
#pragma unroll
        for (int c = 0; c < 8; c++) acc[r][c] = 0.f;

    const int rBase = blockIdx.x * 64;
    const int ti = tid >> 4, tj = tid & 15;    // ti 0..31 (2 rows each), tj 0..15 (8 cols)

    for (int fc = 0; fc < FEAT; fc += 32) {
#pragma unroll
        for (int i = 0; i < 4; i++) {
            int idx = tid + i * 512;            // 0..2047
            int row = idx >> 5, f = idx & 31;
            int gf = fc + f;
            float v = (gf < DIM) ? g_X [(size_t)(rBase + row) * DIM + gf]
                                 : g_Lx[(size_t)(rBase + row) * DIM + (gf - DIM)];
            sH[row][f] = v;
        }
#pragma unroll
        for (int i = 0; i < 8; i++) {
            int idx = tid + i * 512;            // 0..4095
            int f = idx & 31, d = idx >> 5;     // coalesced read along f
            int gf = fc + f;
            sWt[f * 132 + d] = W[d * FEAT + gf] * sS[gf];
        }
        __syncthreads();
#pragma unroll
        for (int f = 0; f < 32; f++) {
            float4 w0 = *(const float4*)&sWt[f * 132 + tj * 4];
            float4 w1 = *(const float4*)&sWt[f * 132 + 64 + tj * 4];
            float hv0 = sH[ti * 2 + 0][f];
            float hv1 = sH[ti * 2 + 1][f];
            float wv[8] = {w0.x, w0.y, w0.z, w0.w, w1.x, w1.y, w1.z, w1.w};
#pragma unroll
            for (int c = 0; c < 8; c++) {
                acc[0][c] += hv0 * wv[c];
                acc[1][c] += hv1 * wv[c];
            }
        }
        __syncthreads();
    }

#pragma unroll
    for (int r = 0; r < 2; r++)
#pragma unroll
        for (int c = 0; c < 8; c++) {
            int row = rBase + ti * 2 + r;
            int col = (c < 4) ? (tj * 4 + c) : (64 + tj * 4 + (c - 4));
            float o = acc[r][c] + sC[col];
            if (residual) o += residual[(size_t)row * DIM + col];
            out[(size_t)row * DIM + col] = o;
        }
}

// ---------------- launch ----------------
extern "C" void kernel_launch(void* const* d_in, const int* in_sizes, int n_in,
                              void* d_out, int out_size)
{
    const float* L      = (const float*)d_in[0];
    // d_in[1] = mask (unused in forward)
    const float* inputs = (const float*)d_in[2];
    const float* bn0_g  = (const float*)d_in[3];
    const float* bn0_b  = (const float*)d_in[4];
    const float* fc0_w  = (const float*)d_in[5];
    const float* fc0_b  = (const float*)d_in[6];
    const float* bn1_g  = (const float*)d_in[7];
    const float* bn1_b  = (const float*)d_in[8];
    const float* fc1_w  = (const float*)d_in[9];
    const float* fc1_b  = (const float*)d_in[10];
    float* out = (float*)d_out;

    cudaFuncSetAttribute((const void*)big_gemm_mma,
                         cudaFuncAttributeMaxDynamicSharedMemorySize, SMEM_BIG);

    dim3 eg(NROWS / 32, DIM / 32), eb(32, 8);
    dim3 gg(NROWS / TBM, 2);

    // ---- block 0 ----
    elu_split_kernel<<<eg, eb>>>(inputs);                 // X = elu(inputs); zeroes stats
    big_gemm_mma<<<gg, 256, SMEM_BIG>>>(L);               // Lp0/Lp1 = split-K partials
    stats_kernel<<<256, 128>>>();                         // reduce partials + column stats
    fold_kernel<<<128, 256>>>(bn0_g, bn0_b, fc0_w, fc0_b);// g_fS, g_fC
    small_gemm_kernel<<<NROWS / 64, 512>>>(fc0_w, nullptr, nullptr);   // -> g_Y

    // ---- block 1 ----
    elu_split_kernel<<<eg, eb>>>(nullptr);                // X = elu(g_Y); zeroes stats
    big_gemm_mma<<<gg, 256, SMEM_BIG>>>(L);
    stats_kernel<<<256, 128>>>();
    fold_kernel<<<128, 256>>>(bn1_g, bn1_b, fc1_w, fc1_b);
    small_gemm_kernel<<<NROWS / 64, 512>>>(fc1_w, inputs, out);  // + residual -> d_out
}